// round 3
// baseline (speedup 1.0000x reference)
#include <cuda_runtime.h>

#define FULLMASK 0xffffffffu

// ---- shared layout (float offsets) ----
#define W2_STRIDE 260                 // 64 x 260 (256 used)
#define W1T_STRIDE 20                 // W1 transposed 64 x 20 (16 used)
#define W1R_STRIDE 68                 // W1 row-major 16 x 68 (64 used)
#define TS 20                         // A-tile row stride
#define TILE 344                      // per-point tile stride (320 used; 344%32=24)
#define WSC_STRIDE 88                 // per-point w scratch (64 used; 88%32=24)
#define USC_STRIDE 24                 // per-point u / dv scratch (16 used)

#define W2S_OFF 0
#define W1T_OFF (64 * W2_STRIDE)                    // 16640
#define W1R_OFF (W1T_OFF + 64 * W1T_STRIDE)         // 17920
#define B1S_OFF (W1R_OFF + 16 * W1R_STRIDE)         // 19008
#define B2S_OFF (B1S_OFF + 64)                      // 19072
#define TILES_OFF (B2S_OFF + 256)                   // 19328
#define WSC_OFF (TILES_OFF + 8 * 4 * TILE)          // 30336
#define USC_OFF (WSC_OFF + 8 * 4 * WSC_STRIDE)      // 33152
#define DSC_OFF (USC_OFF + 32 * USC_STRIDE)         // 33920
#define SMEM_FLOATS (DSC_OFF + 32 * USC_STRIDE)     // 34688
#define SMEM_BYTES (SMEM_FLOATS * 4)                // 138752

// One acceleration evaluation. Warp handles 4 points; lane = (g, sub),
// g = lane>>3 selects the point, sub = lane&7.
// Inputs: this lane's x_{sub}, x_{sub+8}, v_{sub}, v_{sub+8} of point g.
// Returns (dv_{sub}, dv_{sub+8}).
__device__ __noinline__ float2 geo_dv(float xe0, float xe1, float ve0, float ve1,
                                      int lane, int sub, int g, int warp)
{
    extern __shared__ float smem[];
    const float* W2s = smem + W2S_OFF;
    const float* W1t = smem + W1T_OFF;
    const float* W1r = smem + W1R_OFF;
    const float* b1s = smem + B1S_OFF;
    const float* b2s = smem + B2S_OFF;
    float* tiles = smem + TILES_OFF + warp * 4 * TILE;
    float* wsc   = smem + WSC_OFF + (warp * 4 + g) * WSC_STRIDE;
    float* usc   = smem + USC_OFF + warp * 4 * USC_STRIDE;
    float* dsc   = smem + DSC_OFF + warp * 4 * USC_STRIDE;

    const int gbase = lane & 24;

    // ---- replicate x, v of own point into registers (width-8 groups) ----
    float x[16], v[16];
#pragma unroll
    for (int a = 0; a < 8; a++) {
        x[a]     = __shfl_sync(FULLMASK, xe0, gbase + a);
        x[a + 8] = __shfl_sync(FULLMASK, xe1, gbase + a);
        v[a]     = __shfl_sync(FULLMASK, ve0, gbase + a);
        v[a + 8] = __shfl_sync(FULLMASK, ve1, gbase + a);
    }

    // ---- hidden layer: lane owns channels c = sub + 8j of its point ----
    float h[8];
#pragma unroll
    for (int j = 0; j < 8; j++) {
        const int c = sub + 8 * j;
        float pre = b1s[c];
        const float4* wr = (const float4*)(W1t + c * W1T_STRIDE);
#pragma unroll
        for (int t = 0; t < 4; t++) {
            const float4 w = wr[t];
            pre = fmaf(w.x, x[4 * t + 0], pre);
            pre = fmaf(w.y, x[4 * t + 1], pre);
            pre = fmaf(w.z, x[4 * t + 2], pre);
            pre = fmaf(w.w, x[4 * t + 3], pre);
        }
        h[j] = tanhf(pre);
    }

    // ---- A pass: one W2 sweep serves all 4 points ----
    float4 Aa[4], Ab[4];
    {
        const float4 bza = ((const float4*)b2s)[lane];
        const float4 bzb = ((const float4*)b2s)[32 + lane];
#pragma unroll
        for (int p = 0; p < 4; p++) { Aa[p] = bza; Ab[p] = bzb; }
    }
#pragma unroll
    for (int j = 0; j < 8; j++) {
#pragma unroll 4
        for (int rr = 0; rr < 8; rr++) {
            const int r = 8 * j + rr;
            float hp[4];
#pragma unroll
            for (int p = 0; p < 4; p++)
                hp[p] = __shfl_sync(FULLMASK, h[j], p * 8 + rr);
            const float4 wa = *(const float4*)(W2s + r * W2_STRIDE + 4 * lane);
            const float4 wb = *(const float4*)(W2s + r * W2_STRIDE + 128 + 4 * lane);
#pragma unroll
            for (int p = 0; p < 4; p++) {
                Aa[p].x = fmaf(hp[p], wa.x, Aa[p].x);
                Aa[p].y = fmaf(hp[p], wa.y, Aa[p].y);
                Aa[p].z = fmaf(hp[p], wa.z, Aa[p].z);
                Aa[p].w = fmaf(hp[p], wa.w, Aa[p].w);
                Ab[p].x = fmaf(hp[p], wb.x, Ab[p].x);
                Ab[p].y = fmaf(hp[p], wb.y, Ab[p].y);
                Ab[p].z = fmaf(hp[p], wb.z, Ab[p].z);
                Ab[p].w = fmaf(hp[p], wb.w, Ab[p].w);
            }
        }
    }

    // ---- stage A tiles for all 4 points ----
    __syncwarp();
    {
        const int prow = lane >> 2;
        const int qcol = (lane & 3) * 4;
#pragma unroll
        for (int p = 0; p < 4; p++) {
            *(float4*)(tiles + p * TILE + prow * TS + qcol) = Aa[p];
            *(float4*)(tiles + p * TILE + (8 + prow) * TS + qcol) = Ab[p];
        }
    }
    __syncwarp();

    // ---- s = A^T v (own point): lane computes s_{sub}, s_{sub+8} ----
    const float* myt = tiles + g * TILE;
    float s0 = 0.0f, s1 = 0.0f;
#pragma unroll
    for (int p = 0; p < 16; p++) {
        s0 = fmaf(myt[p * TS + sub], v[p], s0);
        s1 = fmaf(myt[p * TS + sub + 8], v[p], s1);
    }
    float sv[16];
#pragma unroll
    for (int q = 0; q < 8; q++) {
        sv[q]     = __shfl_sync(FULLMASK, s0, gbase + q);
        sv[q + 8] = __shfl_sync(FULLMASK, s1, gbase + q);
    }

    // ---- m pass: lane owns rows c = sub + 8j; 4-way broadcast across groups ----
    float w8[8];
#pragma unroll
    for (int j = 0; j < 8; j++) {
        const float* R = W2s + (sub + 8 * j) * W2_STRIDE;
        float m = 0.0f;
#pragma unroll
        for (int p = 0; p < 16; p++) {
            const float4* ch = (const float4*)(R + 16 * p);
            float d = 0.0f;
#pragma unroll
            for (int t = 0; t < 4; t++) {
                const float4 w = ch[t];
                d = fmaf(w.x, sv[4 * t + 0], d);
                d = fmaf(w.y, sv[4 * t + 1], d);
                d = fmaf(w.z, sv[4 * t + 2], d);
                d = fmaf(w.w, sv[4 * t + 3], d);
            }
            m = fmaf(v[p], d, m);
        }
        const float th = fmaf(-h[j], h[j], 1.0f);
        w8[j] = 2.0f * th * m;
    }

    // ---- stage w, compute u rows sub, sub+8 ----
    __syncwarp();
#pragma unroll
    for (int j = 0; j < 8; j++)
        wsc[sub + 8 * j] = w8[j];
    __syncwarp();

    float u0 = 0.0f, u1 = 0.0f;
    {
        const float4* wr0 = (const float4*)(W1r + sub * W1R_STRIDE);
        const float4* wr1 = (const float4*)(W1r + (sub + 8) * W1R_STRIDE);
        const float4* wc = (const float4*)wsc;
#pragma unroll
        for (int t = 0; t < 16; t++) {
            const float4 c = wc[t];
            const float4 a0 = wr0[t];
            const float4 a1 = wr1[t];
            u0 = fmaf(a0.x, c.x, u0); u0 = fmaf(a0.y, c.y, u0);
            u0 = fmaf(a0.z, c.z, u0); u0 = fmaf(a0.w, c.w, u0);
            u1 = fmaf(a1.x, c.x, u1); u1 = fmaf(a1.y, c.y, u1);
            u1 = fmaf(a1.z, c.z, u1); u1 = fmaf(a1.w, c.w, u1);
        }
    }
    usc[g * USC_STRIDE + sub] = u0;
    usc[g * USC_STRIDE + sub + 8] = u1;
    __syncwarp();

    // ---- g-build + SPD solve: 2 rounds, 16 lanes per point (R2-proven code) ----
    const int half = lane >> 4;
    const int i16 = lane & 15;
#pragma unroll
    for (int r = 0; r < 2; r++) {
        const int lp = 2 * r + half;
        const float* T = tiles + lp * TILE;

        float ar[16];
#pragma unroll
        for (int t = 0; t < 4; t++) {
            const float4 w = *(const float4*)(T + i16 * TS + 4 * t);
            ar[4 * t + 0] = w.x; ar[4 * t + 1] = w.y;
            ar[4 * t + 2] = w.z; ar[4 * t + 3] = w.w;
        }
        float grow[16];
#pragma unroll
        for (int jr = 0; jr < 16; jr++) {
            float gj = (jr == i16) ? 1.0f : 0.0f;
#pragma unroll
            for (int t = 0; t < 4; t++) {
                const float4 w = *(const float4*)(T + jr * TS + 4 * t);  // half-broadcast
                gj = fmaf(ar[4 * t + 0], w.x, gj);
                gj = fmaf(ar[4 * t + 1], w.y, gj);
                gj = fmaf(ar[4 * t + 2], w.z, gj);
                gj = fmaf(ar[4 * t + 3], w.w, gj);
            }
            grow[jr] = gj;
        }
        float rhs = usc[lp * USC_STRIDE + i16];

#pragma unroll
        for (int k = 0; k < 15; k++) {
            const float piv = __shfl_sync(FULLMASK, grow[k], k, 16);
            const float prhs = __shfl_sync(FULLMASK, rhs, k, 16);
            const float ipiv = __fdividef(1.0f, piv);
            const float fac = grow[k] * ipiv;
            const bool act = (i16 > k);
#pragma unroll
            for (int q = k + 1; q < 16; q++) {
                const float pq = __shfl_sync(FULLMASK, grow[q], k, 16);
                if (act) grow[q] = fmaf(-fac, pq, grow[q]);
            }
            if (act) rhs = fmaf(-fac, prhs, rhs);
        }
        float dvl = 0.0f;
#pragma unroll
        for (int k = 15; k >= 0; k--) {
            const float num = __shfl_sync(FULLMASK, rhs, k, 16);
            const float den = __shfl_sync(FULLMASK, grow[k], k, 16);
            const float yk = __fdividef(num, den);
            if (i16 < k) rhs = fmaf(-grow[k], yk, rhs);
            if (i16 == k) dvl = -0.5f * yk;
        }
        dsc[lp * USC_STRIDE + i16] = dvl;
    }
    __syncwarp();

    float2 res;
    res.x = dsc[g * USC_STRIDE + sub];
    res.y = dsc[g * USC_STRIDE + sub + 8];
    return res;
}

__global__ __launch_bounds__(256, 1)
void NeuralGeodesicFlows_45784351375900_kernel(
    const float* __restrict__ z_in,
    const float* __restrict__ t_ptr,
    const float* __restrict__ W1,
    const float* __restrict__ b1,
    const float* __restrict__ W2,
    const float* __restrict__ b2,
    const int* __restrict__ ns_ptr,
    float* __restrict__ z_out,
    int B)
{
    extern __shared__ float smem[];
    const int tid = threadIdx.x;

    // cooperative weight staging
    for (int idx = tid; idx < 64 * 256; idx += 256)
        smem[W2S_OFF + (idx >> 8) * W2_STRIDE + (idx & 255)] = W2[idx];
    for (int idx = tid; idx < 16 * 64; idx += 256) {
        const int a = idx >> 6, c = idx & 63;
        const float w = W1[idx];
        smem[W1R_OFF + a * W1R_STRIDE + c] = w;
        smem[W1T_OFF + c * W1T_STRIDE + a] = w;
    }
    if (tid < 64) smem[B1S_OFF + tid] = b1[tid];
    smem[B2S_OFF + tid] = b2[tid];
    __syncthreads();

    const int warp = tid >> 5;
    const int lane = tid & 31;
    const int sub = lane & 7;
    const int g = lane >> 3;
    const int point = blockIdx.x * 32 + warp * 4 + g;
    if (point >= B) return;

    const float* zp = z_in + point * 32;
    float xs0 = zp[sub];
    float xs1 = zp[sub + 8];
    float vs0 = zp[16 + sub];
    float vs1 = zp[24 + sub];

    const float t = *t_ptr;
    const int ns = *ns_ptr;
    const float dt = t / (float)ns;
    const float hdt = 0.5f * dt;
    const float dt6 = dt * (1.0f / 6.0f);

    for (int s = 0; s < ns; s++) {
        const float2 a1 = geo_dv(xs0, xs1, vs0, vs1, lane, sub, g, warp);
        const float v20 = fmaf(hdt, a1.x, vs0);
        const float v21 = fmaf(hdt, a1.y, vs1);
        const float2 a2 = geo_dv(fmaf(hdt, vs0, xs0), fmaf(hdt, vs1, xs1),
                                 v20, v21, lane, sub, g, warp);
        const float v30 = fmaf(hdt, a2.x, vs0);
        const float v31 = fmaf(hdt, a2.y, vs1);
        const float2 a3 = geo_dv(fmaf(hdt, v20, xs0), fmaf(hdt, v21, xs1),
                                 v30, v31, lane, sub, g, warp);
        const float v40 = fmaf(dt, a3.x, vs0);
        const float v41 = fmaf(dt, a3.y, vs1);
        const float2 a4 = geo_dv(fmaf(dt, v30, xs0), fmaf(dt, v31, xs1),
                                 v40, v41, lane, sub, g, warp);
        xs0 = fmaf(dt6, vs0 + 2.0f * v20 + 2.0f * v30 + v40, xs0);
        xs1 = fmaf(dt6, vs1 + 2.0f * v21 + 2.0f * v31 + v41, xs1);
        vs0 = fmaf(dt6, a1.x + 2.0f * a2.x + 2.0f * a3.x + a4.x, vs0);
        vs1 = fmaf(dt6, a1.y + 2.0f * a2.y + 2.0f * a3.y + a4.y, vs1);
    }

    float* op = z_out + point * 32;
    op[sub] = xs0;
    op[sub + 8] = xs1;
    op[16 + sub] = vs0;
    op[24 + sub] = vs1;
}

extern "C" void kernel_launch(void* const* d_in, const int* in_sizes, int n_in,
                              void* d_out, int out_size)
{
    const float* z  = (const float*)d_in[0];
    const float* t  = (const float*)d_in[1];
    const float* W1 = (const float*)d_in[2];
    const float* b1 = (const float*)d_in[3];
    const float* W2 = (const float*)d_in[4];
    const float* b2 = (const float*)d_in[5];
    const int*   ns = (const int*)d_in[6];
    float* out = (float*)d_out;

    const int B = in_sizes[0] / 32;
    const int grid = (B + 31) / 32;

    cudaFuncSetAttribute(NeuralGeodesicFlows_45784351375900_kernel,
                         cudaFuncAttributeMaxDynamicSharedMemorySize, SMEM_BYTES);
    NeuralGeodesicFlows_45784351375900_kernel<<<grid, 256, SMEM_BYTES>>>(
        z, t, W1, b1, W2, b2, ns, out, B);
}

// round 4
// speedup vs baseline: 1.1973x; 1.1973x over previous
#include <cuda_runtime.h>

#define FULLMASK 0xffffffffu

// ---- shared layout (float offsets), one 512-thread block (16 warps) ----
#define W2_STRIDE 260
#define W1T_STRIDE 20
#define W1R_STRIDE 68
#define TS 20
#define TILE 344
#define SV_STRIDE 24
#define TH_STRIDE 72
#define WSC_STRIDE 88
#define USC_STRIDE 24

#define W2S_OFF 0
#define W1T_OFF (64 * W2_STRIDE)                   // 16640
#define W1R_OFF (W1T_OFF + 64 * W1T_STRIDE)        // 17920
#define B1S_OFF (W1R_OFF + 16 * W1R_STRIDE)        // 19008
#define B2S_OFF (B1S_OFF + 64)                     // 19072
#define TILES_OFF (B2S_OFF + 256)                  // 19328
#define SVSC_OFF (TILES_OFF + 16 * 4 * TILE)       // 41344
#define VSC_OFF (SVSC_OFF + 16 * 4 * SV_STRIDE)    // 42880
#define THSC_OFF (VSC_OFF + 16 * 4 * SV_STRIDE)    // 44416
#define WSC_OFF (THSC_OFF + 16 * 4 * TH_STRIDE)    // 49024
#define USC_OFF (WSC_OFF + 16 * 4 * WSC_STRIDE)    // 54656
#define DSC_OFF (USC_OFF + 64 * USC_STRIDE)        // 56192
#define SMEM_FLOATS (DSC_OFF + 64 * USC_STRIDE)    // 57728
#define SMEM_BYTES (SMEM_FLOATS * 4)               // 230912

// One acceleration evaluation. Warp handles 4 points.
// A-pass grouping: lane = (g, sub), g = lane>>3 (point), sub = lane&7.
// m-pass grouping: lane = (half, i16), half owns points 2h, 2h+1.
__device__ __noinline__ float2 geo_dv(float xe0, float xe1, float ve0, float ve1,
                                      int lane, int sub, int g, int warp)
{
    extern __shared__ float smem[];
    const float* W2s = smem + W2S_OFF;
    const float* W1t = smem + W1T_OFF;
    const float* W1r = smem + W1R_OFF;
    const float* b1s = smem + B1S_OFF;
    const float* b2s = smem + B2S_OFF;
    float* tiles = smem + TILES_OFF + warp * 4 * TILE;
    float* svsc  = smem + SVSC_OFF + warp * 4 * SV_STRIDE;
    float* vsc   = smem + VSC_OFF + warp * 4 * SV_STRIDE;
    float* thsc  = smem + THSC_OFF + warp * 4 * TH_STRIDE;
    float* wsc   = smem + WSC_OFF + warp * 4 * WSC_STRIDE;
    float* usc   = smem + USC_OFF + warp * 4 * USC_STRIDE;
    float* dsc   = smem + DSC_OFF + warp * 4 * USC_STRIDE;

    const int gbase = lane & 24;

    // ---- stage v of own point (needed by m-pass in half-warp layout) ----
    __syncwarp();
    vsc[g * SV_STRIDE + sub] = ve0;
    vsc[g * SV_STRIDE + sub + 8] = ve1;

    // ---- replicate x, v of own point (width-8 groups) ----
    float x[16], v[16];
#pragma unroll
    for (int a = 0; a < 8; a++) {
        x[a]     = __shfl_sync(FULLMASK, xe0, gbase + a);
        x[a + 8] = __shfl_sync(FULLMASK, xe1, gbase + a);
        v[a]     = __shfl_sync(FULLMASK, ve0, gbase + a);
        v[a + 8] = __shfl_sync(FULLMASK, ve1, gbase + a);
    }

    // ---- hidden layer: lane owns channels c = sub + 8j of its point ----
    float h[8];
#pragma unroll
    for (int j = 0; j < 8; j++) {
        const int c = sub + 8 * j;
        float pre = b1s[c];
        const float4* wr = (const float4*)(W1t + c * W1T_STRIDE);
#pragma unroll
        for (int t = 0; t < 4; t++) {
            const float4 w = wr[t];
            pre = fmaf(w.x, x[4 * t + 0], pre);
            pre = fmaf(w.y, x[4 * t + 1], pre);
            pre = fmaf(w.z, x[4 * t + 2], pre);
            pre = fmaf(w.w, x[4 * t + 3], pre);
        }
        h[j] = tanhf(pre);
        thsc[g * TH_STRIDE + c] = fmaf(-h[j], h[j], 1.0f);   // th = 1 - h^2
    }

    // ---- A pass: one W2 sweep serves all 4 points ----
    float4 Aa[4], Ab[4];
    {
        const float4 bza = ((const float4*)b2s)[lane];
        const float4 bzb = ((const float4*)b2s)[32 + lane];
#pragma unroll
        for (int p = 0; p < 4; p++) { Aa[p] = bza; Ab[p] = bzb; }
    }
#pragma unroll
    for (int j = 0; j < 8; j++) {
#pragma unroll 4
        for (int rr = 0; rr < 8; rr++) {
            const int r = 8 * j + rr;
            float hp[4];
#pragma unroll
            for (int p = 0; p < 4; p++)
                hp[p] = __shfl_sync(FULLMASK, h[j], p * 8 + rr);
            const float4 wa = *(const float4*)(W2s + r * W2_STRIDE + 4 * lane);
            const float4 wb = *(const float4*)(W2s + r * W2_STRIDE + 128 + 4 * lane);
#pragma unroll
            for (int p = 0; p < 4; p++) {
                Aa[p].x = fmaf(hp[p], wa.x, Aa[p].x);
                Aa[p].y = fmaf(hp[p], wa.y, Aa[p].y);
                Aa[p].z = fmaf(hp[p], wa.z, Aa[p].z);
                Aa[p].w = fmaf(hp[p], wa.w, Aa[p].w);
                Ab[p].x = fmaf(hp[p], wb.x, Ab[p].x);
                Ab[p].y = fmaf(hp[p], wb.y, Ab[p].y);
                Ab[p].z = fmaf(hp[p], wb.z, Ab[p].z);
                Ab[p].w = fmaf(hp[p], wb.w, Ab[p].w);
            }
        }
    }

    // ---- stage A tiles ----
    __syncwarp();
    {
        const int prow = lane >> 2;
        const int qcol = (lane & 3) * 4;
#pragma unroll
        for (int p = 0; p < 4; p++) {
            *(float4*)(tiles + p * TILE + prow * TS + qcol) = Aa[p];
            *(float4*)(tiles + p * TILE + (8 + prow) * TS + qcol) = Ab[p];
        }
    }
    __syncwarp();

    // ---- s = A^T v (own point), stage sv to smem ----
    {
        const float* myt = tiles + g * TILE;
        float s0 = 0.0f, s1 = 0.0f;
#pragma unroll
        for (int p = 0; p < 16; p++) {
            s0 = fmaf(myt[p * TS + sub], v[p], s0);
            s1 = fmaf(myt[p * TS + sub + 8], v[p], s1);
        }
        svsc[g * SV_STRIDE + sub] = s0;
        svsc[g * SV_STRIDE + sub + 8] = s1;
    }
    __syncwarp();

    // ---- m pass: half-warp layout. half owns points pA=2h, pB=2h+1.
    //      lane (half, i16) owns rows c = i16 + 16j; each W2 read feeds 2 points ----
    const int half = lane >> 4;
    const int i16 = lane & 15;
    {
        const int pA = 2 * half, pB = 2 * half + 1;
        float svA[16], svB[16], vA[16], vB[16];
#pragma unroll
        for (int t = 0; t < 4; t++) {
            const float4 a = *(const float4*)(svsc + pA * SV_STRIDE + 4 * t);
            const float4 b = *(const float4*)(svsc + pB * SV_STRIDE + 4 * t);
            const float4 c = *(const float4*)(vsc + pA * SV_STRIDE + 4 * t);
            const float4 d = *(const float4*)(vsc + pB * SV_STRIDE + 4 * t);
            svA[4 * t + 0] = a.x; svA[4 * t + 1] = a.y; svA[4 * t + 2] = a.z; svA[4 * t + 3] = a.w;
            svB[4 * t + 0] = b.x; svB[4 * t + 1] = b.y; svB[4 * t + 2] = b.z; svB[4 * t + 3] = b.w;
            vA[4 * t + 0] = c.x; vA[4 * t + 1] = c.y; vA[4 * t + 2] = c.z; vA[4 * t + 3] = c.w;
            vB[4 * t + 0] = d.x; vB[4 * t + 1] = d.y; vB[4 * t + 2] = d.z; vB[4 * t + 3] = d.w;
        }
#pragma unroll
        for (int j = 0; j < 4; j++) {
            const int c = i16 + 16 * j;
            const float* R = W2s + c * W2_STRIDE;
            float mA = 0.0f, mB = 0.0f;
#pragma unroll
            for (int p = 0; p < 16; p++) {
                const float4* ch = (const float4*)(R + 16 * p);
                float dA = 0.0f, dB = 0.0f;
#pragma unroll
                for (int t = 0; t < 4; t++) {
                    const float4 w = ch[t];
                    dA = fmaf(w.x, svA[4 * t + 0], dA);
                    dA = fmaf(w.y, svA[4 * t + 1], dA);
                    dA = fmaf(w.z, svA[4 * t + 2], dA);
                    dA = fmaf(w.w, svA[4 * t + 3], dA);
                    dB = fmaf(w.x, svB[4 * t + 0], dB);
                    dB = fmaf(w.y, svB[4 * t + 1], dB);
                    dB = fmaf(w.z, svB[4 * t + 2], dB);
                    dB = fmaf(w.w, svB[4 * t + 3], dB);
                }
                mA = fmaf(vA[p], dA, mA);
                mB = fmaf(vB[p], dB, mB);
            }
            const float thA = thsc[pA * TH_STRIDE + c];
            const float thB = thsc[pB * TH_STRIDE + c];
            wsc[pA * WSC_STRIDE + c] = 2.0f * thA * mA;
            wsc[pB * WSC_STRIDE + c] = 2.0f * thB * mB;
        }
    }
    __syncwarp();

    // ---- u rows sub, sub+8 of own point (group layout) ----
    {
        float u0 = 0.0f, u1 = 0.0f;
        const float4* wr0 = (const float4*)(W1r + sub * W1R_STRIDE);
        const float4* wr1 = (const float4*)(W1r + (sub + 8) * W1R_STRIDE);
        const float4* wc = (const float4*)(wsc + g * WSC_STRIDE);
#pragma unroll
        for (int t = 0; t < 16; t++) {
            const float4 cc = wc[t];
            const float4 a0 = wr0[t];
            const float4 a1 = wr1[t];
            u0 = fmaf(a0.x, cc.x, u0); u0 = fmaf(a0.y, cc.y, u0);
            u0 = fmaf(a0.z, cc.z, u0); u0 = fmaf(a0.w, cc.w, u0);
            u1 = fmaf(a1.x, cc.x, u1); u1 = fmaf(a1.y, cc.y, u1);
            u1 = fmaf(a1.z, cc.z, u1); u1 = fmaf(a1.w, cc.w, u1);
        }
        usc[g * USC_STRIDE + sub] = u0;
        usc[g * USC_STRIDE + sub + 8] = u1;
    }
    __syncwarp();

    // ---- g-build + SPD solve: 2 rounds, 16 lanes per point ----
#pragma unroll
    for (int r = 0; r < 2; r++) {
        const int lp = 2 * r + half;
        const float* T = tiles + lp * TILE;

        float ar[16];
#pragma unroll
        for (int t = 0; t < 4; t++) {
            const float4 w = *(const float4*)(T + i16 * TS + 4 * t);
            ar[4 * t + 0] = w.x; ar[4 * t + 1] = w.y;
            ar[4 * t + 2] = w.z; ar[4 * t + 3] = w.w;
        }
        float grow[16];
#pragma unroll
        for (int jr = 0; jr < 16; jr++) {
            float gj = (jr == i16) ? 1.0f : 0.0f;
#pragma unroll
            for (int t = 0; t < 4; t++) {
                const float4 w = *(const float4*)(T + jr * TS + 4 * t);
                gj = fmaf(ar[4 * t + 0], w.x, gj);
                gj = fmaf(ar[4 * t + 1], w.y, gj);
                gj = fmaf(ar[4 * t + 2], w.z, gj);
                gj = fmaf(ar[4 * t + 3], w.w, gj);
            }
            grow[jr] = gj;
        }
        float rhs = usc[lp * USC_STRIDE + i16];

#pragma unroll
        for (int k = 0; k < 15; k++) {
            const float piv = __shfl_sync(FULLMASK, grow[k], k, 16);
            const float prhs = __shfl_sync(FULLMASK, rhs, k, 16);
            const float ipiv = __fdividef(1.0f, piv);
            const float fac = grow[k] * ipiv;
            const bool act = (i16 > k);
#pragma unroll
            for (int q = k + 1; q < 16; q++) {
                const float pq = __shfl_sync(FULLMASK, grow[q], k, 16);
                if (act) grow[q] = fmaf(-fac, pq, grow[q]);
            }
            if (act) rhs = fmaf(-fac, prhs, rhs);
        }
        float dvl = 0.0f;
#pragma unroll
        for (int k = 15; k >= 0; k--) {
            const float num = __shfl_sync(FULLMASK, rhs, k, 16);
            const float den = __shfl_sync(FULLMASK, grow[k], k, 16);
            const float yk = __fdividef(num, den);
            if (i16 < k) rhs = fmaf(-grow[k], yk, rhs);
            if (i16 == k) dvl = -0.5f * yk;
        }
        dsc[lp * USC_STRIDE + i16] = dvl;
    }
    __syncwarp();

    float2 res;
    res.x = dsc[g * USC_STRIDE + sub];
    res.y = dsc[g * USC_STRIDE + sub + 8];
    return res;
}

__global__ __launch_bounds__(512, 1)
void NeuralGeodesicFlows_45784351375900_kernel(
    const float* __restrict__ z_in,
    const float* __restrict__ t_ptr,
    const float* __restrict__ W1,
    const float* __restrict__ b1,
    const float* __restrict__ W2,
    const float* __restrict__ b2,
    const int* __restrict__ ns_ptr,
    float* __restrict__ z_out,
    int B)
{
    extern __shared__ float smem[];
    const int tid = threadIdx.x;

    // cooperative weight staging
    for (int idx = tid; idx < 64 * 256; idx += 512)
        smem[W2S_OFF + (idx >> 8) * W2_STRIDE + (idx & 255)] = W2[idx];
    for (int idx = tid; idx < 16 * 64; idx += 512) {
        const int a = idx >> 6, c = idx & 63;
        const float w = W1[idx];
        smem[W1R_OFF + a * W1R_STRIDE + c] = w;
        smem[W1T_OFF + c * W1T_STRIDE + a] = w;
    }
    if (tid < 64) smem[B1S_OFF + tid] = b1[tid];
    if (tid < 256) smem[B2S_OFF + tid] = b2[tid];
    __syncthreads();

    const int warp = tid >> 5;
    const int lane = tid & 31;
    const int sub = lane & 7;
    const int g = lane >> 3;
    const int point = blockIdx.x * 64 + warp * 4 + g;
    if (point >= B) return;

    const float* zp = z_in + point * 32;
    float xs0 = zp[sub];
    float xs1 = zp[sub + 8];
    float vs0 = zp[16 + sub];
    float vs1 = zp[24 + sub];

    const float t = *t_ptr;
    const int ns = *ns_ptr;
    const float dt = t / (float)ns;
    const float hdt = 0.5f * dt;
    const float dt6 = dt * (1.0f / 6.0f);

    for (int s = 0; s < ns; s++) {
        const float2 a1 = geo_dv(xs0, xs1, vs0, vs1, lane, sub, g, warp);
        const float v20 = fmaf(hdt, a1.x, vs0);
        const float v21 = fmaf(hdt, a1.y, vs1);
        const float2 a2 = geo_dv(fmaf(hdt, vs0, xs0), fmaf(hdt, vs1, xs1),
                                 v20, v21, lane, sub, g, warp);
        const float v30 = fmaf(hdt, a2.x, vs0);
        const float v31 = fmaf(hdt, a2.y, vs1);
        const float2 a3 = geo_dv(fmaf(hdt, v20, xs0), fmaf(hdt, v21, xs1),
                                 v30, v31, lane, sub, g, warp);
        const float v40 = fmaf(dt, a3.x, vs0);
        const float v41 = fmaf(dt, a3.y, vs1);
        const float2 a4 = geo_dv(fmaf(dt, v30, xs0), fmaf(dt, v31, xs1),
                                 v40, v41, lane, sub, g, warp);
        xs0 = fmaf(dt6, vs0 + 2.0f * v20 + 2.0f * v30 + v40, xs0);
        xs1 = fmaf(dt6, vs1 + 2.0f * v21 + 2.0f * v31 + v41, xs1);
        vs0 = fmaf(dt6, a1.x + 2.0f * a2.x + 2.0f * a3.x + a4.x, vs0);
        vs1 = fmaf(dt6, a1.y + 2.0f * a2.y + 2.0f * a3.y + a4.y, vs1);
    }

    float* op = z_out + point * 32;
    op[sub] = xs0;
    op[sub + 8] = xs1;
    op[16 + sub] = vs0;
    op[24 + sub] = vs1;
}

extern "C" void kernel_launch(void* const* d_in, const int* in_sizes, int n_in,
                              void* d_out, int out_size)
{
    const float* z  = (const float*)d_in[0];
    const float* t  = (const float*)d_in[1];
    const float* W1 = (const float*)d_in[2];
    const float* b1 = (const float*)d_in[3];
    const float* W2 = (const float*)d_in[4];
    const float* b2 = (const float*)d_in[5];
    const int*   ns = (const int*)d_in[6];
    float* out = (float*)d_out;

    const int B = in_sizes[0] / 32;
    const int grid = (B + 63) / 64;

    cudaFuncSetAttribute(NeuralGeodesicFlows_45784351375900_kernel,
                         cudaFuncAttributeMaxDynamicSharedMemorySize, SMEM_BYTES);
    NeuralGeodesicFlows_45784351375900_kernel<<<grid, 512, SMEM_BYTES>>>(
        z, t, W1, b1, W2, b2, ns, out, B);
}